// round 1
// baseline (speedup 1.0000x reference)
#include <cuda_runtime.h>

#define NUM_GRAPHS 1000
#define NPG 500
#define EPG 8000
#define E_TOT (NUM_GRAPHS * EPG)
#define F 16
#define C_OUT 11
#define NT 512
#define HSTRIDE 501   // odd stride -> conflict-free feature-major access

struct SmemT {
    float bufS[F * HSTRIDE];   // scaled h1 (dis[c]*h1), later h2
    float bufR[F * HSTRIDE];   // raw h1, later lx
    float xs[NPG];
    float xss[NPG];            // dis[c]*x[c]
    float dis[NPG];
    float W2s[F * F];
    float W1s[F], b1s[F], b2s[F];
    float W3s[F * C_OUT], b3s[C_OUT + 5];
    float pooled[F];
    int   row_start[NPG + 1];
    int   pos[NPG];
    int   warpsum[16];
    unsigned short ccsr[EPG];
};

__global__ void __launch_bounds__(NT, 2) gnn_kernel(
    const float* __restrict__ x, const int* __restrict__ ei,
    const float* __restrict__ W1, const float* __restrict__ b1,
    const float* __restrict__ W2, const float* __restrict__ b2,
    const float* __restrict__ W3, const float* __restrict__ b3,
    float* __restrict__ out)
{
    extern __shared__ unsigned char raw[];
    SmemT* sm = reinterpret_cast<SmemT*>(raw);
    const int tid = threadIdx.x;
    const int g = blockIdx.x;
    const int base = g * NPG;
    const int* srcp = ei + (size_t)g * EPG;
    const int* dstp = ei + (size_t)E_TOT + (size_t)g * EPG;

    // ---- load weights + x, zero counters ----
    for (int i = tid; i < F * F; i += NT) sm->W2s[i] = W2[i];
    for (int i = tid; i < F * C_OUT; i += NT) sm->W3s[i] = W3[i];
    if (tid < F) { sm->W1s[tid] = W1[tid]; sm->b1s[tid] = b1[tid]; sm->b2s[tid] = b2[tid]; }
    if (tid < C_OUT) sm->b3s[tid] = b3[tid];
    if (tid < NPG) { sm->xs[tid] = x[base + tid]; sm->pos[tid] = 0; }
    __syncthreads();

    // ---- pass A: per-row edge counts (deg over src) ----
    for (int e = tid; e < EPG; e += NT) {
        int s = srcp[e] - base;
        atomicAdd(&sm->pos[s], 1);
    }
    __syncthreads();

    // ---- block scan -> row_start; dis = rsqrt(deg) ----
    int cnt0 = (tid < NPG) ? sm->pos[tid] : 0;
    int v = cnt0;
    #pragma unroll
    for (int o = 1; o < 32; o <<= 1) {
        int nv = __shfl_up_sync(0xFFFFFFFFu, v, o);
        if ((tid & 31) >= o) v += nv;
    }
    if ((tid & 31) == 31) sm->warpsum[tid >> 5] = v;
    __syncthreads();
    if (tid < 32) {
        int s = (tid < 16) ? sm->warpsum[tid] : 0;
        #pragma unroll
        for (int o = 1; o < 32; o <<= 1) {
            int nv = __shfl_up_sync(0xFFFFFFFFu, s, o);
            if (tid >= o) s += nv;
        }
        if (tid < 16) sm->warpsum[tid] = s;
    }
    __syncthreads();
    int inc = v + ((tid >= 32) ? sm->warpsum[(tid >> 5) - 1] : 0);
    if (tid == 0) sm->row_start[0] = 0;
    if (tid < NPG) {
        sm->row_start[tid + 1] = inc;
        sm->pos[tid] = inc - cnt0;           // exclusive offset = fill cursor
        float d = (cnt0 > 0) ? rsqrtf((float)cnt0) : 0.f;
        sm->dis[tid] = d;
        sm->xss[tid] = d * sm->xs[tid];
    }
    __syncthreads();

    // ---- pass B: fill CSR (local u16 col indices) ----
    for (int e = tid; e < EPG; e += NT) {
        int s = srcp[e] - base;
        int d = dstp[e] - base;
        int p = atomicAdd(&sm->pos[s], 1);
        sm->ccsr[p] = (unsigned short)d;
    }
    __syncthreads();

    // ---- layer 1: scalar gather + 1->16 expand, store raw + scaled ----
    if (tid < NPG) {
        const int r = tid;
        const int s0 = sm->row_start[r], s1 = sm->row_start[r + 1];
        float acc = 0.f;
        for (int t = s0; t < s1; t++) acc += sm->xss[sm->ccsr[t]];
        const float dr = sm->dis[r];
        const float lx1 = sm->xs[r] - dr * acc;
        #pragma unroll
        for (int j = 0; j < F; j++) {
            float h = fmaxf(fmaf(lx1, sm->W1s[j], sm->b1s[j]), 0.f);
            sm->bufR[j * HSTRIDE + r] = h;
            sm->bufS[j * HSTRIDE + r] = dr * h;
        }
    }
    __syncthreads();

    // ---- layer 2 gather: 16 lanes (= features) per row, 32 row-groups ----
    {
        const int lane16 = tid & 15, grp = tid >> 4;
        const float* bs = sm->bufS + lane16 * HSTRIDE;
        float* br = sm->bufR + lane16 * HSTRIDE;
        for (int r = grp; r < NPG; r += NT / 16) {
            const int s0 = sm->row_start[r], s1 = sm->row_start[r + 1];
            float acc = 0.f;
            int t = s0;
            for (; t + 1 < s1; t += 2) {
                int c0 = sm->ccsr[t], c1 = sm->ccsr[t + 1];
                acc += bs[c0];
                acc += bs[c1];
            }
            if (t < s1) acc += bs[sm->ccsr[t]];
            br[r] = br[r] - sm->dis[r] * acc;   // lx overwrites raw h1 (safe: only self reads raw[r])
        }
    }
    __syncthreads();

    // ---- layer 2 dense 16x16 + relu -> bufS (h2) ----
    {
        const int lane16 = tid & 15, grp = tid >> 4;
        float w2k[F];
        #pragma unroll
        for (int j = 0; j < F; j++) w2k[j] = sm->W2s[j * F + lane16];
        const float bk = sm->b2s[lane16];
        for (int r = grp; r < NPG; r += NT / 16) {
            float s = bk;
            #pragma unroll
            for (int j = 0; j < F; j++) s = fmaf(sm->bufR[j * HSTRIDE + r], w2k[j], s);
            sm->bufS[lane16 * HSTRIDE + r] = fmaxf(s, 0.f);
        }
    }
    __syncthreads();

    // ---- mean pool (warp w = feature w) + final 16->11 linear ----
    {
        const int w = tid >> 5, l = tid & 31;   // 16 warps == F features
        float s = 0.f;
        for (int n = l; n < NPG; n += 32) s += sm->bufS[w * HSTRIDE + n];
        #pragma unroll
        for (int o = 16; o; o >>= 1) s += __shfl_xor_sync(0xFFFFFFFFu, s, o);
        if (l == 0) sm->pooled[w] = s * (1.0f / NPG);
    }
    __syncthreads();
    if (tid < C_OUT) {
        float o = sm->b3s[tid];
        #pragma unroll
        for (int k = 0; k < F; k++) o = fmaf(sm->pooled[k], sm->W3s[k * C_OUT + tid], o);
        out[(size_t)g * C_OUT + tid] = o;
    }
}

extern "C" void kernel_launch(void* const* d_in, const int* in_sizes, int n_in,
                              void* d_out, int out_size)
{
    const float* x  = (const float*)d_in[0];
    const int*   ei = (const int*)d_in[1];
    // d_in[2] = graph_id (unused: layout is contiguous/deterministic)
    const float* W1 = (const float*)d_in[3];
    const float* b1 = (const float*)d_in[4];
    const float* W2 = (const float*)d_in[5];
    const float* b2 = (const float*)d_in[6];
    const float* W3 = (const float*)d_in[7];
    const float* b3 = (const float*)d_in[8];

    cudaFuncSetAttribute(gnn_kernel, cudaFuncAttributeMaxDynamicSharedMemorySize,
                         (int)sizeof(SmemT));
    gnn_kernel<<<NUM_GRAPHS, NT, sizeof(SmemT)>>>(x, ei, W1, b1, W2, b2, W3, b3,
                                                  (float*)d_out);
}